// round 9
// baseline (speedup 1.0000x reference)
#include <cuda_runtime.h>
#include <cuda_bf16.h>

#define NMAX 100000
#define EMAX 3700000
#define F 256
#define H 32
#define C 40

// Scratch (allocation-free rule: __device__ globals)
__device__ __align__(16) int   g_cnt_src[NMAX];
__device__ __align__(16) int   g_cnt_dst[NMAX];
__device__ __align__(16) float g_norm_src[NMAX];
__device__ __align__(16) float g_norm_dst[NMAX];
__device__ __align__(16) int   g_rowptr[NMAX + 1];
__device__ __align__(16) int   g_cursor[NMAX];
__device__ __align__(16) int   g_col[EMAX];             // CSR by dst: src indices
__device__ __align__(16) float g_h1[NMAX * H];          // (x*ns) @ W1
__device__ __align__(16) float g_h2[NMAX * C];          // (relu(agg1*nd+b1)*ns) @ W2

// ---------------------------------------------------------------- zero counts
__global__ void k_zero(int N) {
    int i = blockIdx.x * blockDim.x + threadIdx.x;
    int stride = gridDim.x * blockDim.x;
    for (int t = i; t < N; t += stride) { g_cnt_src[t] = 0; g_cnt_dst[t] = 0; }
}

// ---------------------------------------------------------------- degree counts
__global__ void k_count(const int* __restrict__ src, const int* __restrict__ dst, int E) {
    int i = blockIdx.x * blockDim.x + threadIdx.x;
    if (i >= E) return;
    atomicAdd(&g_cnt_src[src[i]], 1);
    atomicAdd(&g_cnt_dst[dst[i]], 1);
}

__global__ void k_norm(int N) {
    int i = blockIdx.x * blockDim.x + threadIdx.x;
    if (i >= N) return;
    g_norm_src[i] = rsqrtf((float)g_cnt_src[i]);   // self-loops guarantee deg >= 1
    g_norm_dst[i] = rsqrtf((float)g_cnt_dst[i]);
}

// ---------------------------------------------------------------- exclusive scan of cnt_dst -> rowptr (+cursor copy)
// Single block, 1024 threads, each thread owns a contiguous chunk.
__global__ void k_scan(int N, int E) {
    __shared__ int ps[1024];
    int t = threadIdx.x;
    int chunk = (N + 1023) >> 10;
    int beg = t * chunk;
    int end = min(beg + chunk, N);
    int s = 0;
    for (int i = beg; i < end; i++) s += g_cnt_dst[i];
    ps[t] = s;
    __syncthreads();
    // Hillis-Steele inclusive scan
    for (int off = 1; off < 1024; off <<= 1) {
        int v = (t >= off) ? ps[t - off] : 0;
        __syncthreads();
        ps[t] += v;
        __syncthreads();
    }
    int run = ps[t] - s;   // exclusive prefix for this thread's chunk
    for (int i = beg; i < end; i++) {
        g_rowptr[i] = run;
        g_cursor[i] = run;
        run += g_cnt_dst[i];
    }
    if (t == 1023) g_rowptr[N] = E;
}

// ---------------------------------------------------------------- fill CSR (order within a node irrelevant: sum)
__global__ void k_fill(const int* __restrict__ src, const int* __restrict__ dst, int E) {
    int i = blockIdx.x * blockDim.x + threadIdx.x;
    if (i >= E) return;
    int d = dst[i];
    int pos = atomicAdd(&g_cursor[d], 1);
    if (pos < EMAX) g_col[pos] = src[i];
}

// ---------------------------------------------------------------- GEMM1: h1 = (x * norm_src) @ W1
// 32 rows/block, 256 threads. W1 in smem, X tile double-buffered with register prefetch.
__global__ void k_gemm1(const float* __restrict__ x, const float* __restrict__ W1, int N) {
    __shared__ __align__(16) float Ws[F * H];        // 32 KB
    __shared__ __align__(16) float Xs[2][32 * 32];   // 8 KB
    const int tid = threadIdx.x;
    const int lane = tid & 31;
    const int w = tid >> 5;          // 0..7
    const int row0 = blockIdx.x * 32;

    for (int i = tid; i < (F * H) / 4; i += 256)
        ((float4*)Ws)[i] = ((const float4*)W1)[i];

    // this thread's X-load slot: one float4 per tile
    const int lrow = tid >> 3;            // 0..31
    const int lf4  = tid & 7;             // float4 index within 32-float row slice
    const int grow = row0 + lrow;
    const bool valid = (grow < N);
    const float4* xrow = (const float4*)(x + (valid ? grow : 0) * F);

    float4 f4 = make_float4(0.f, 0.f, 0.f, 0.f);
    if (valid) f4 = xrow[lf4];            // tile 0
    *(float4*)&Xs[0][lrow * 32 + lf4 * 4] = f4;
    __syncthreads();

    float acc[4] = {0.f, 0.f, 0.f, 0.f};

    #pragma unroll
    for (int t = 0; t < 8; t++) {
        // prefetch next tile into registers (overlaps with compute below)
        if (t < 7 && valid) f4 = xrow[(t + 1) * 8 + lf4];
        const float* Xc = &Xs[t & 1][0];
        #pragma unroll
        for (int k = 0; k < 32; k += 4) {
            int gk = t * 32 + k;
            float wv0 = Ws[(gk + 0) * H + lane];
            float wv1 = Ws[(gk + 1) * H + lane];
            float wv2 = Ws[(gk + 2) * H + lane];
            float wv3 = Ws[(gk + 3) * H + lane];
            #pragma unroll
            for (int r = 0; r < 4; r++) {
                float4 xv = *(const float4*)&Xc[(w * 4 + r) * 32 + k];
                acc[r] += xv.x * wv0 + xv.y * wv1 + xv.z * wv2 + xv.w * wv3;
            }
        }
        __syncthreads();
        if (t < 7) {
            *(float4*)&Xs[(t + 1) & 1][lrow * 32 + lf4 * 4] = f4;
            __syncthreads();
        }
    }
    #pragma unroll
    for (int r = 0; r < 4; r++) {
        int row = row0 + w * 4 + r;
        if (row < N) g_h1[row * H + lane] = acc[r] * g_norm_src[row];
    }
}

// ---------------------------------------------------------------- Layer 1 fused:
// per node: agg1 = sum_{e in CSR[n]} h1[col[e]];  x1 = relu(agg1*nd + b1) * ns;
// h2[n] = x1 @ W2  (shuffle GEMM, x1 one float per lane)
__global__ void k_layer1(const float* __restrict__ b1, const float* __restrict__ W2, int N) {
    __shared__ float Ws[H * C];   // 5 KB
    const int tid = threadIdx.x;
    const int lane = tid & 31;
    const int w = tid >> 5;
    for (int i = tid; i < H * C; i += 256) Ws[i] = W2[i];
    __syncthreads();

    int n = blockIdx.x * 8 + w;
    if (n >= N) return;

    int beg = g_rowptr[n], end = g_rowptr[n + 1];
    float acc = 0.f;
    int e = beg;
    for (; e + 4 <= end; e += 4) {
        int s0 = g_col[e], s1 = g_col[e + 1], s2 = g_col[e + 2], s3 = g_col[e + 3];
        float v0 = g_h1[s0 * H + lane];
        float v1 = g_h1[s1 * H + lane];
        float v2 = g_h1[s2 * H + lane];
        float v3 = g_h1[s3 * H + lane];
        acc += (v0 + v1) + (v2 + v3);
    }
    for (; e < end; e++) acc += g_h1[g_col[e] * H + lane];

    float x1 = fmaxf(fmaf(acc, g_norm_dst[n], b1[lane]), 0.f) * g_norm_src[n];

    float o0 = 0.f, o1 = 0.f;
    #pragma unroll
    for (int k = 0; k < H; k++) {
        float xk = __shfl_sync(0xffffffffu, x1, k);
        o0 = fmaf(xk, Ws[k * C + lane], o0);
        o1 = fmaf(xk, (lane < 8) ? Ws[k * C + 32 + lane] : 0.f, o1);
    }
    g_h2[n * C + lane] = o0;
    if (lane < 8) g_h2[n * C + 32 + lane] = o1;
}

// ---------------------------------------------------------------- Layer 2 fused:
// per node: agg2 = sum h2[col[e]];  v = agg2*nd + b2;  out[n] = log_softmax(v)
__global__ void k_layer2(const float* __restrict__ b2, float* __restrict__ out, int N) {
    const int tid = threadIdx.x;
    const int lane = tid & 31;
    const int w = tid >> 5;
    int n = blockIdx.x * 8 + w;
    if (n >= N) return;

    int beg = g_rowptr[n], end = g_rowptr[n + 1];
    float a0 = 0.f, a1 = 0.f;
    int e = beg;
    for (; e + 2 <= end; e += 2) {
        int s0 = g_col[e], s1 = g_col[e + 1];
        float u0 = g_h2[s0 * C + lane];
        float u1 = g_h2[s1 * C + lane];
        float p0 = (lane < 8) ? g_h2[s0 * C + 32 + lane] : 0.f;
        float p1 = (lane < 8) ? g_h2[s1 * C + 32 + lane] : 0.f;
        a0 += u0 + u1;
        a1 += p0 + p1;
    }
    for (; e < end; e++) {
        int s = g_col[e];
        a0 += g_h2[s * C + lane];
        if (lane < 8) a1 += g_h2[s * C + 32 + lane];
    }

    float nd = g_norm_dst[n];
    float v0 = fmaf(a0, nd, b2[lane]);
    float v1 = (lane < 8) ? fmaf(a1, nd, b2[32 + lane]) : -1e30f;

    float m = fmaxf(v0, v1);
    #pragma unroll
    for (int off = 16; off > 0; off >>= 1)
        m = fmaxf(m, __shfl_xor_sync(0xffffffffu, m, off));
    float s = __expf(v0 - m) + ((lane < 8) ? __expf(v1 - m) : 0.f);
    #pragma unroll
    for (int off = 16; off > 0; off >>= 1)
        s += __shfl_xor_sync(0xffffffffu, s, off);
    float lse = m + __logf(s);

    out[n * C + lane] = v0 - lse;
    if (lane < 8) out[n * C + 32 + lane] = v1 - lse;
}

// ---------------------------------------------------------------- launch
extern "C" void kernel_launch(void* const* d_in, const int* in_sizes, int n_in,
                              void* d_out, int out_size) {
    const float* feat = (const float*)d_in[0];
    const int*   src  = (const int*)d_in[1];
    const int*   dst  = (const int*)d_in[2];
    const float* W1   = (const float*)d_in[3];
    const float* b1   = (const float*)d_in[4];
    const float* W2   = (const float*)d_in[5];
    const float* b2   = (const float*)d_in[6];
    float* out = (float*)d_out;

    const int N = in_sizes[0] / F;
    const int E = in_sizes[1];

    k_zero<<<128, 256>>>(N);
    k_count<<<(E + 255) / 256, 256>>>(src, dst, E);
    k_norm<<<(N + 255) / 256, 256>>>(N);
    k_scan<<<1, 1024>>>(N, E);
    k_fill<<<(E + 255) / 256, 256>>>(src, dst, E);
    k_gemm1<<<(N + 31) / 32, 256>>>(feat, W1, N);
    k_layer1<<<(N + 7) / 8, 256>>>(b1, W2, N);
    k_layer2<<<(N + 7) / 8, 256>>>(b2, out, N);
}

// round 11
// speedup vs baseline: 2.4124x; 2.4124x over previous
#include <cuda_runtime.h>
#include <cuda_bf16.h>

#define NMAX 100000
#define EMAX 3700000
#define F 256
#define H 32
#define C 40

// Scratch (allocation-free rule: __device__ globals)
__device__ __align__(16) int   g_cnt_src[NMAX];
__device__ __align__(16) int   g_cnt_dst[NMAX];
__device__ __align__(16) float g_norm_src[NMAX];
__device__ __align__(16) float g_norm_dst[NMAX];
__device__ __align__(16) int   g_rowbeg[NMAX];
__device__ __align__(16) int   g_cursor[NMAX];
__device__              int    g_total;
__device__ __align__(16) int   g_col[EMAX];             // CSR-ish by dst: src indices (slices unordered)
__device__ __align__(16) float g_h1[NMAX * H];          // (x*ns) @ W1
__device__ __align__(16) float g_h2[NMAX * C];          // (relu(agg1*nd+b1)*ns) @ W2

// ---------------------------------------------------------------- zero counts
__global__ void k_zero(int N) {
    int i = blockIdx.x * blockDim.x + threadIdx.x;
    int stride = gridDim.x * blockDim.x;
    if (i == 0) g_total = 0;
    for (int t = i; t < N; t += stride) { g_cnt_src[t] = 0; g_cnt_dst[t] = 0; }
}

// ---------------------------------------------------------------- degree counts
__global__ void k_count(const int* __restrict__ src, const int* __restrict__ dst, int E) {
    int i = blockIdx.x * blockDim.x + threadIdx.x;
    if (i >= E) return;
    atomicAdd(&g_cnt_src[src[i]], 1);
    atomicAdd(&g_cnt_dst[dst[i]], 1);
}

// ---------------------------------------------------------------- allocate slices + norms
// Warp-aggregated atomic allocation: slice order across nodes is irrelevant (per-node sum).
__global__ void k_alloc(int N) {
    int i = blockIdx.x * blockDim.x + threadIdx.x;
    int lane = threadIdx.x & 31;
    int cnt = (i < N) ? g_cnt_dst[i] : 0;

    int incl = cnt;
    #pragma unroll
    for (int off = 1; off < 32; off <<= 1) {
        int v = __shfl_up_sync(0xffffffffu, incl, off);
        if (lane >= off) incl += v;
    }
    int total = __shfl_sync(0xffffffffu, incl, 31);
    int base = 0;
    if (lane == 31 && total > 0) base = atomicAdd(&g_total, total);
    base = __shfl_sync(0xffffffffu, base, 31);

    if (i < N) {
        int beg = base + incl - cnt;
        g_rowbeg[i] = beg;
        g_cursor[i] = beg;
        g_norm_src[i] = rsqrtf((float)g_cnt_src[i]);   // self-loops guarantee deg >= 1
        g_norm_dst[i] = rsqrtf((float)cnt);
    }
}

// ---------------------------------------------------------------- fill slices
__global__ void k_fill(const int* __restrict__ src, const int* __restrict__ dst, int E) {
    int i = blockIdx.x * blockDim.x + threadIdx.x;
    if (i >= E) return;
    int d = dst[i];
    int pos = atomicAdd(&g_cursor[d], 1);
    if (pos < EMAX) g_col[pos] = src[i];
}

// ---------------------------------------------------------------- GEMM1: h1 = (x * norm_src) @ W1
// 32 rows/block, 256 threads. W1 in smem, X tile double-buffered with register prefetch.
__global__ void k_gemm1(const float* __restrict__ x, const float* __restrict__ W1, int N) {
    __shared__ __align__(16) float Ws[F * H];        // 32 KB
    __shared__ __align__(16) float Xs[2][32 * 32];   // 8 KB
    const int tid = threadIdx.x;
    const int lane = tid & 31;
    const int w = tid >> 5;          // 0..7
    const int row0 = blockIdx.x * 32;

    for (int i = tid; i < (F * H) / 4; i += 256)
        ((float4*)Ws)[i] = ((const float4*)W1)[i];

    const int lrow = tid >> 3;            // 0..31
    const int lf4  = tid & 7;             // float4 index within 32-float row slice
    const int grow = row0 + lrow;
    const bool valid = (grow < N);
    const float4* xrow = (const float4*)(x + (valid ? grow : 0) * F);

    float4 f4 = make_float4(0.f, 0.f, 0.f, 0.f);
    if (valid) f4 = xrow[lf4];            // tile 0
    *(float4*)&Xs[0][lrow * 32 + lf4 * 4] = f4;
    __syncthreads();

    float acc[4] = {0.f, 0.f, 0.f, 0.f};

    #pragma unroll
    for (int t = 0; t < 8; t++) {
        if (t < 7 && valid) f4 = xrow[(t + 1) * 8 + lf4];   // prefetch next tile
        const float* Xc = &Xs[t & 1][0];
        #pragma unroll
        for (int k = 0; k < 32; k += 4) {
            int gk = t * 32 + k;
            float wv0 = Ws[(gk + 0) * H + lane];
            float wv1 = Ws[(gk + 1) * H + lane];
            float wv2 = Ws[(gk + 2) * H + lane];
            float wv3 = Ws[(gk + 3) * H + lane];
            #pragma unroll
            for (int r = 0; r < 4; r++) {
                float4 xv = *(const float4*)&Xc[(w * 4 + r) * 32 + k];
                acc[r] += xv.x * wv0 + xv.y * wv1 + xv.z * wv2 + xv.w * wv3;
            }
        }
        __syncthreads();
        if (t < 7) {
            *(float4*)&Xs[(t + 1) & 1][lrow * 32 + lf4 * 4] = f4;
            __syncthreads();
        }
    }
    #pragma unroll
    for (int r = 0; r < 4; r++) {
        int row = row0 + w * 4 + r;
        if (row < N) g_h1[row * H + lane] = acc[r] * g_norm_src[row];
    }
}

// ---------------------------------------------------------------- Layer 1 fused:
// per node: agg1 = sum_{e in slice[n]} h1[col[e]];  x1 = relu(agg1*nd + b1) * ns;
// h2[n] = x1 @ W2  (shuffle GEMM, x1 one float per lane)
__global__ void k_layer1(const float* __restrict__ b1, const float* __restrict__ W2, int N) {
    __shared__ float Ws[H * C];   // 5 KB
    const int tid = threadIdx.x;
    const int lane = tid & 31;
    const int w = tid >> 5;
    for (int i = tid; i < H * C; i += 256) Ws[i] = W2[i];
    __syncthreads();

    int n = blockIdx.x * 8 + w;
    if (n >= N) return;

    int beg = g_rowbeg[n];
    int end = beg + g_cnt_dst[n];
    float acc = 0.f;
    int e = beg;
    for (; e + 8 <= end; e += 8) {
        int s0 = g_col[e],     s1 = g_col[e + 1], s2 = g_col[e + 2], s3 = g_col[e + 3];
        int s4 = g_col[e + 4], s5 = g_col[e + 5], s6 = g_col[e + 6], s7 = g_col[e + 7];
        float v0 = g_h1[s0 * H + lane];
        float v1 = g_h1[s1 * H + lane];
        float v2 = g_h1[s2 * H + lane];
        float v3 = g_h1[s3 * H + lane];
        float v4 = g_h1[s4 * H + lane];
        float v5 = g_h1[s5 * H + lane];
        float v6 = g_h1[s6 * H + lane];
        float v7 = g_h1[s7 * H + lane];
        acc += ((v0 + v1) + (v2 + v3)) + ((v4 + v5) + (v6 + v7));
    }
    for (; e < end; e++) acc += g_h1[g_col[e] * H + lane];

    float x1 = fmaxf(fmaf(acc, g_norm_dst[n], b1[lane]), 0.f) * g_norm_src[n];

    float o0 = 0.f, o1 = 0.f;
    #pragma unroll
    for (int k = 0; k < H; k++) {
        float xk = __shfl_sync(0xffffffffu, x1, k);
        o0 = fmaf(xk, Ws[k * C + lane], o0);
        o1 = fmaf(xk, (lane < 8) ? Ws[k * C + 32 + lane] : 0.f, o1);
    }
    g_h2[n * C + lane] = o0;
    if (lane < 8) g_h2[n * C + 32 + lane] = o1;
}

// ---------------------------------------------------------------- Layer 2 fused:
// per node: agg2 = sum h2[col[e]];  v = agg2*nd + b2;  out[n] = log_softmax(v)
__global__ void k_layer2(const float* __restrict__ b2, float* __restrict__ out, int N) {
    const int tid = threadIdx.x;
    const int lane = tid & 31;
    const int w = tid >> 5;
    int n = blockIdx.x * 8 + w;
    if (n >= N) return;

    int beg = g_rowbeg[n];
    int end = beg + g_cnt_dst[n];
    float a0 = 0.f, a1 = 0.f;
    int e = beg;
    for (; e + 4 <= end; e += 4) {
        int s0 = g_col[e], s1 = g_col[e + 1], s2 = g_col[e + 2], s3 = g_col[e + 3];
        float u0 = g_h2[s0 * C + lane];
        float u1 = g_h2[s1 * C + lane];
        float u2 = g_h2[s2 * C + lane];
        float u3 = g_h2[s3 * C + lane];
        float p0 = (lane < 8) ? g_h2[s0 * C + 32 + lane] : 0.f;
        float p1 = (lane < 8) ? g_h2[s1 * C + 32 + lane] : 0.f;
        float p2 = (lane < 8) ? g_h2[s2 * C + 32 + lane] : 0.f;
        float p3 = (lane < 8) ? g_h2[s3 * C + 32 + lane] : 0.f;
        a0 += (u0 + u1) + (u2 + u3);
        a1 += (p0 + p1) + (p2 + p3);
    }
    for (; e < end; e++) {
        int s = g_col[e];
        a0 += g_h2[s * C + lane];
        if (lane < 8) a1 += g_h2[s * C + 32 + lane];
    }

    float nd = g_norm_dst[n];
    float v0 = fmaf(a0, nd, b2[lane]);
    float v1 = (lane < 8) ? fmaf(a1, nd, b2[32 + lane]) : -1e30f;

    float m = fmaxf(v0, v1);
    #pragma unroll
    for (int off = 16; off > 0; off >>= 1)
        m = fmaxf(m, __shfl_xor_sync(0xffffffffu, m, off));
    float s = __expf(v0 - m) + ((lane < 8) ? __expf(v1 - m) : 0.f);
    #pragma unroll
    for (int off = 16; off > 0; off >>= 1)
        s += __shfl_xor_sync(0xffffffffu, s, off);
    float lse = m + __logf(s);

    out[n * C + lane] = v0 - lse;
    if (lane < 8) out[n * C + 32 + lane] = v1 - lse;
}

// ---------------------------------------------------------------- launch
extern "C" void kernel_launch(void* const* d_in, const int* in_sizes, int n_in,
                              void* d_out, int out_size) {
    const float* feat = (const float*)d_in[0];
    const int*   src  = (const int*)d_in[1];
    const int*   dst  = (const int*)d_in[2];
    const float* W1   = (const float*)d_in[3];
    const float* b1   = (const float*)d_in[4];
    const float* W2   = (const float*)d_in[5];
    const float* b2   = (const float*)d_in[6];
    float* out = (float*)d_out;

    const int N = in_sizes[0] / F;
    const int E = in_sizes[1];

    k_zero<<<128, 256>>>(N);
    k_count<<<(E + 255) / 256, 256>>>(src, dst, E);
    k_alloc<<<(N + 255) / 256, 256>>>(N);
    k_fill<<<(E + 255) / 256, 256>>>(src, dst, E);
    k_gemm1<<<(N + 31) / 32, 256>>>(feat, W1, N);
    k_layer1<<<(N + 7) / 8, 256>>>(b1, W2, N);
    k_layer2<<<(N + 7) / 8, 256>>>(b2, out, N);
}

// round 14
// speedup vs baseline: 2.4148x; 1.0010x over previous
#include <cuda_runtime.h>
#include <cuda_bf16.h>

#define NMAX 100000
#define EMAX 3700000
#define F 256
#define H 32
#define C 40

// Scratch (allocation-free rule: __device__ globals)
__device__ __align__(16) int   g_cnt_src[NMAX];
__device__ __align__(16) int   g_cnt_dst[NMAX];
__device__ __align__(16) float g_norm_src[NMAX];
__device__ __align__(16) float g_norm_dst[NMAX];
__device__ __align__(16) int   g_rowbeg[NMAX];
__device__ __align__(16) int   g_cursor[NMAX];
__device__              int    g_total;
__device__ __align__(16) int   g_col[EMAX];             // CSR-ish by dst: src indices (slices unordered)
__device__ __align__(16) float g_h1[NMAX * H];          // (x*ns) @ W1
__device__ __align__(16) float g_h2[NMAX * C];          // (relu(agg1*nd+b1)*ns) @ W2

// ---------------------------------------------------------------- zero counts
__global__ void k_zero(int N) {
    int i = blockIdx.x * blockDim.x + threadIdx.x;
    int stride = gridDim.x * blockDim.x;
    if (i == 0) g_total = 0;
    for (int t = i; t < N; t += stride) { g_cnt_src[t] = 0; g_cnt_dst[t] = 0; }
}

// ---------------------------------------------------------------- degree counts (4 edges/thread, int4 loads)
__global__ void k_count(const int* __restrict__ src, const int* __restrict__ dst, int E) {
    int base = (blockIdx.x * blockDim.x + threadIdx.x) * 4;
    if (base + 3 < E) {
        int4 s = *(const int4*)(src + base);
        int4 d = *(const int4*)(dst + base);
        atomicAdd(&g_cnt_src[s.x], 1);
        atomicAdd(&g_cnt_src[s.y], 1);
        atomicAdd(&g_cnt_src[s.z], 1);
        atomicAdd(&g_cnt_src[s.w], 1);
        atomicAdd(&g_cnt_dst[d.x], 1);
        atomicAdd(&g_cnt_dst[d.y], 1);
        atomicAdd(&g_cnt_dst[d.z], 1);
        atomicAdd(&g_cnt_dst[d.w], 1);
    } else {
        for (int i = base; i < E; i++) {
            atomicAdd(&g_cnt_src[src[i]], 1);
            atomicAdd(&g_cnt_dst[dst[i]], 1);
        }
    }
}

// ---------------------------------------------------------------- allocate slices + norms
// Warp-aggregated atomic allocation: slice order across nodes is irrelevant (per-node sum).
__global__ void k_alloc(int N) {
    int i = blockIdx.x * blockDim.x + threadIdx.x;
    int lane = threadIdx.x & 31;
    int cnt = (i < N) ? g_cnt_dst[i] : 0;

    int incl = cnt;
    #pragma unroll
    for (int off = 1; off < 32; off <<= 1) {
        int v = __shfl_up_sync(0xffffffffu, incl, off);
        if (lane >= off) incl += v;
    }
    int total = __shfl_sync(0xffffffffu, incl, 31);
    int base = 0;
    if (lane == 31 && total > 0) base = atomicAdd(&g_total, total);
    base = __shfl_sync(0xffffffffu, base, 31);

    if (i < N) {
        int beg = base + incl - cnt;
        g_rowbeg[i] = beg;
        g_cursor[i] = beg;
        g_norm_src[i] = rsqrtf((float)g_cnt_src[i]);   // self-loops guarantee deg >= 1
        g_norm_dst[i] = rsqrtf((float)cnt);
    }
}

// ---------------------------------------------------------------- fill slices (4 edges/thread, int4 loads)
__global__ void k_fill(const int* __restrict__ src, const int* __restrict__ dst, int E) {
    int base = (blockIdx.x * blockDim.x + threadIdx.x) * 4;
    if (base + 3 < E) {
        int4 s = *(const int4*)(src + base);
        int4 d = *(const int4*)(dst + base);
        int p0 = atomicAdd(&g_cursor[d.x], 1);
        int p1 = atomicAdd(&g_cursor[d.y], 1);
        int p2 = atomicAdd(&g_cursor[d.z], 1);
        int p3 = atomicAdd(&g_cursor[d.w], 1);
        if (p0 < EMAX) g_col[p0] = s.x;
        if (p1 < EMAX) g_col[p1] = s.y;
        if (p2 < EMAX) g_col[p2] = s.z;
        if (p3 < EMAX) g_col[p3] = s.w;
    } else {
        for (int i = base; i < E; i++) {
            int pos = atomicAdd(&g_cursor[dst[i]], 1);
            if (pos < EMAX) g_col[pos] = src[i];
        }
    }
}

// ---------------------------------------------------------------- GEMM1: h1 = (x * norm_src) @ W1
// 64 rows/block, 512 threads (16 warps), cp.async double-buffered X tiles.
__global__ void __launch_bounds__(512) k_gemm1(const float* __restrict__ x,
                                               const float* __restrict__ W1, int N) {
    __shared__ __align__(16) float Ws[F * H];        // 32 KB
    __shared__ __align__(16) float Xs[2][64 * 32];   // 16 KB
    const int tid = threadIdx.x;
    const int lane = tid & 31;
    const int w = tid >> 5;          // 0..15
    const int row0 = blockIdx.x * 64;

    for (int i = tid; i < (F * H) / 4; i += 512)
        ((float4*)Ws)[i] = ((const float4*)W1)[i];

    // each thread owns one float4 slot per tile
    const int lrow = tid >> 3;            // 0..63
    const int lf4  = tid & 7;             // float4 idx within 32-float row slice
    const int grow = row0 + lrow;
    const bool valid = (grow < N);
    const float* gsrc = x + (long long)(valid ? grow : 0) * F + lf4 * 4;
    const unsigned sdst0 = (unsigned)__cvta_generic_to_shared(&Xs[0][lrow * 32 + lf4 * 4]);
    const unsigned sdst1 = (unsigned)__cvta_generic_to_shared(&Xs[1][lrow * 32 + lf4 * 4]);
    const int nbytes = valid ? 16 : 0;    // 0 -> zero-fill 16B

    asm volatile("cp.async.cg.shared.global [%0], [%1], 16, %2;"
                 :: "r"(sdst0), "l"(gsrc), "r"(nbytes));
    asm volatile("cp.async.commit_group;");

    float acc[4] = {0.f, 0.f, 0.f, 0.f};

    #pragma unroll
    for (int t = 0; t < 8; t++) {
        if (t < 7) {
            // buffer (t+1)&1 was last read in iter t-1; end-of-iter sync makes this safe
            unsigned sd = ((t + 1) & 1) ? sdst1 : sdst0;
            asm volatile("cp.async.cg.shared.global [%0], [%1], 16, %2;"
                         :: "r"(sd), "l"(gsrc + (t + 1) * 32), "r"(nbytes));
            asm volatile("cp.async.commit_group;");
            asm volatile("cp.async.wait_group 1;");   // tile t arrived
        } else {
            asm volatile("cp.async.wait_group 0;");
        }
        __syncthreads();
        const float* Xc = &Xs[t & 1][0];
        #pragma unroll
        for (int k = 0; k < 32; k += 4) {
            int gk = t * 32 + k;
            float wv0 = Ws[(gk + 0) * H + lane];
            float wv1 = Ws[(gk + 1) * H + lane];
            float wv2 = Ws[(gk + 2) * H + lane];
            float wv3 = Ws[(gk + 3) * H + lane];
            #pragma unroll
            for (int r = 0; r < 4; r++) {
                float4 xv = *(const float4*)&Xc[(w * 4 + r) * 32 + k];
                acc[r] += xv.x * wv0 + xv.y * wv1 + xv.z * wv2 + xv.w * wv3;
            }
        }
        __syncthreads();
    }
    #pragma unroll
    for (int r = 0; r < 4; r++) {
        int row = row0 + w * 4 + r;
        if (row < N) g_h1[row * H + lane] = acc[r] * g_norm_src[row];
    }
}

// ---------------------------------------------------------------- Layer 1 fused:
// per node: agg1 = sum_{e in slice[n]} h1[col[e]];  x1 = relu(agg1*nd + b1) * ns;
// h2[n] = x1 @ W2  (shuffle GEMM, x1 one float per lane)
__global__ void k_layer1(const float* __restrict__ b1, const float* __restrict__ W2, int N) {
    __shared__ float Ws[H * C];   // 5 KB
    const int tid = threadIdx.x;
    const int lane = tid & 31;
    const int w = tid >> 5;
    for (int i = tid; i < H * C; i += 256) Ws[i] = W2[i];
    __syncthreads();

    int n = blockIdx.x * 8 + w;
    if (n >= N) return;

    int beg = g_rowbeg[n];
    int end = beg + g_cnt_dst[n];
    float acc = 0.f;
    int e = beg;
    for (; e + 8 <= end; e += 8) {
        int s0 = g_col[e],     s1 = g_col[e + 1], s2 = g_col[e + 2], s3 = g_col[e + 3];
        int s4 = g_col[e + 4], s5 = g_col[e + 5], s6 = g_col[e + 6], s7 = g_col[e + 7];
        float v0 = g_h1[s0 * H + lane];
        float v1 = g_h1[s1 * H + lane];
        float v2 = g_h1[s2 * H + lane];
        float v3 = g_h1[s3 * H + lane];
        float v4 = g_h1[s4 * H + lane];
        float v5 = g_h1[s5 * H + lane];
        float v6 = g_h1[s6 * H + lane];
        float v7 = g_h1[s7 * H + lane];
        acc += ((v0 + v1) + (v2 + v3)) + ((v4 + v5) + (v6 + v7));
    }
    for (; e < end; e++) acc += g_h1[g_col[e] * H + lane];

    float x1 = fmaxf(fmaf(acc, g_norm_dst[n], b1[lane]), 0.f) * g_norm_src[n];

    float o0 = 0.f, o1 = 0.f;
    #pragma unroll
    for (int k = 0; k < H; k++) {
        float xk = __shfl_sync(0xffffffffu, x1, k);
        o0 = fmaf(xk, Ws[k * C + lane], o0);
        o1 = fmaf(xk, (lane < 8) ? Ws[k * C + 32 + lane] : 0.f, o1);
    }
    g_h2[n * C + lane] = o0;
    if (lane < 8) g_h2[n * C + 32 + lane] = o1;
}

// ---------------------------------------------------------------- Layer 2 fused:
// per node: agg2 = sum h2[col[e]];  v = agg2*nd + b2;  out[n] = log_softmax(v)
__global__ void k_layer2(const float* __restrict__ b2, float* __restrict__ out, int N) {
    const int tid = threadIdx.x;
    const int lane = tid & 31;
    const int w = tid >> 5;
    int n = blockIdx.x * 8 + w;
    if (n >= N) return;

    int beg = g_rowbeg[n];
    int end = beg + g_cnt_dst[n];
    float a0 = 0.f, a1 = 0.f;
    int e = beg;
    for (; e + 4 <= end; e += 4) {
        int s0 = g_col[e], s1 = g_col[e + 1], s2 = g_col[e + 2], s3 = g_col[e + 3];
        float u0 = g_h2[s0 * C + lane];
        float u1 = g_h2[s1 * C + lane];
        float u2 = g_h2[s2 * C + lane];
        float u3 = g_h2[s3 * C + lane];
        float p0 = (lane < 8) ? g_h2[s0 * C + 32 + lane] : 0.f;
        float p1 = (lane < 8) ? g_h2[s1 * C + 32 + lane] : 0.f;
        float p2 = (lane < 8) ? g_h2[s2 * C + 32 + lane] : 0.f;
        float p3 = (lane < 8) ? g_h2[s3 * C + 32 + lane] : 0.f;
        a0 += (u0 + u1) + (u2 + u3);
        a1 += (p0 + p1) + (p2 + p3);
    }
    for (; e < end; e++) {
        int s = g_col[e];
        a0 += g_h2[s * C + lane];
        if (lane < 8) a1 += g_h2[s * C + 32 + lane];
    }

    float nd = g_norm_dst[n];
    float v0 = fmaf(a0, nd, b2[lane]);
    float v1 = (lane < 8) ? fmaf(a1, nd, b2[32 + lane]) : -1e30f;

    float m = fmaxf(v0, v1);
    #pragma unroll
    for (int off = 16; off > 0; off >>= 1)
        m = fmaxf(m, __shfl_xor_sync(0xffffffffu, m, off));
    float s = __expf(v0 - m) + ((lane < 8) ? __expf(v1 - m) : 0.f);
    #pragma unroll
    for (int off = 16; off > 0; off >>= 1)
        s += __shfl_xor_sync(0xffffffffu, s, off);
    float lse = m + __logf(s);

    out[n * C + lane] = v0 - lse;
    if (lane < 8) out[n * C + 32 + lane] = v1 - lse;
}

// ---------------------------------------------------------------- launch
extern "C" void kernel_launch(void* const* d_in, const int* in_sizes, int n_in,
                              void* d_out, int out_size) {
    const float* feat = (const float*)d_in[0];
    const int*   src  = (const int*)d_in[1];
    const int*   dst  = (const int*)d_in[2];
    const float* W1   = (const float*)d_in[3];
    const float* b1   = (const float*)d_in[4];
    const float* W2   = (const float*)d_in[5];
    const float* b2   = (const float*)d_in[6];
    float* out = (float*)d_out;

    const int N = in_sizes[0] / F;
    const int E = in_sizes[1];

    k_zero<<<128, 256>>>(N);
    k_count<<<(E + 1023) / 1024, 256>>>(src, dst, E);
    k_alloc<<<(N + 255) / 256, 256>>>(N);
    k_fill<<<(E + 1023) / 1024, 256>>>(src, dst, E);
    k_gemm1<<<(N + 63) / 64, 512>>>(feat, W1, N);
    k_layer1<<<(N + 7) / 8, 256>>>(b1, W2, N);
    k_layer2<<<(N + 7) / 8, 256>>>(b2, out, N);
}

// round 16
// speedup vs baseline: 2.4628x; 1.0199x over previous
#include <cuda_runtime.h>
#include <cuda_bf16.h>

#define NMAX 100000
#define EMAX 3700000
#define F 256
#define H 32
#define C 40

// Scratch (allocation-free rule: __device__ globals)
__device__ __align__(16) int   g_cnt_src[NMAX];
__device__ __align__(16) int   g_cnt_dst[NMAX];
__device__ __align__(16) float g_norm_src[NMAX];
__device__ __align__(16) float g_norm_dst[NMAX];
__device__ __align__(16) int   g_rowbeg[NMAX];
__device__              int    g_total;
__device__ __align__(16) int   g_seq[EMAX];             // per-edge rank within its dst
__device__ __align__(16) int   g_col[EMAX];             // CSR-ish by dst: src indices (slices unordered)
__device__ __align__(16) float g_h1[NMAX * H];          // (x*ns) @ W1
__device__ __align__(16) float g_h2[NMAX * C];          // (relu(agg1*nd+b1)*ns) @ W2

// ---------------------------------------------------------------- zero counts
__global__ void k_zero(int N) {
    int i = blockIdx.x * blockDim.x + threadIdx.x;
    int stride = gridDim.x * blockDim.x;
    if (i == 0) g_total = 0;
    for (int t = i; t < N; t += stride) { g_cnt_src[t] = 0; g_cnt_dst[t] = 0; }
}

// ---------------------------------------------------------------- pass1: count + rank
// One atomic-return per edge on dst (gives count AND slot rank); RED on src count.
__global__ void k_pass1(const int* __restrict__ src, const int* __restrict__ dst, int E) {
    int base = (blockIdx.x * blockDim.x + threadIdx.x) * 4;
    if (base + 3 < E) {
        int4 s = *(const int4*)(src + base);
        int4 d = *(const int4*)(dst + base);
        int q0 = atomicAdd(&g_cnt_dst[d.x], 1);
        int q1 = atomicAdd(&g_cnt_dst[d.y], 1);
        int q2 = atomicAdd(&g_cnt_dst[d.z], 1);
        int q3 = atomicAdd(&g_cnt_dst[d.w], 1);
        *(int4*)(g_seq + base) = make_int4(q0, q1, q2, q3);
        atomicAdd(&g_cnt_src[s.x], 1);
        atomicAdd(&g_cnt_src[s.y], 1);
        atomicAdd(&g_cnt_src[s.z], 1);
        atomicAdd(&g_cnt_src[s.w], 1);
    } else {
        for (int i = base; i < E; i++) {
            g_seq[i] = atomicAdd(&g_cnt_dst[dst[i]], 1);
            atomicAdd(&g_cnt_src[src[i]], 1);
        }
    }
}

// ---------------------------------------------------------------- allocate slices + norms
// Warp-aggregated atomic allocation: slice order across nodes is irrelevant (per-node sum).
__global__ void k_alloc(int N) {
    int i = blockIdx.x * blockDim.x + threadIdx.x;
    int lane = threadIdx.x & 31;
    int cnt = (i < N) ? g_cnt_dst[i] : 0;

    int incl = cnt;
    #pragma unroll
    for (int off = 1; off < 32; off <<= 1) {
        int v = __shfl_up_sync(0xffffffffu, incl, off);
        if (lane >= off) incl += v;
    }
    int total = __shfl_sync(0xffffffffu, incl, 31);
    int base = 0;
    if (lane == 31 && total > 0) base = atomicAdd(&g_total, total);
    base = __shfl_sync(0xffffffffu, base, 31);

    if (i < N) {
        g_rowbeg[i] = base + incl - cnt;
        g_norm_src[i] = rsqrtf((float)g_cnt_src[i]);   // self-loops guarantee deg >= 1
        g_norm_dst[i] = rsqrtf((float)cnt);
    }
}

// ---------------------------------------------------------------- pass2: scatter fill, no atomics
__global__ void k_pass2(const int* __restrict__ src, const int* __restrict__ dst, int E) {
    int base = (blockIdx.x * blockDim.x + threadIdx.x) * 4;
    if (base + 3 < E) {
        int4 s = *(const int4*)(src + base);
        int4 d = *(const int4*)(dst + base);
        int4 q = *(const int4*)(g_seq + base);
        int p0 = g_rowbeg[d.x] + q.x;
        int p1 = g_rowbeg[d.y] + q.y;
        int p2 = g_rowbeg[d.z] + q.z;
        int p3 = g_rowbeg[d.w] + q.w;
        if (p0 < EMAX) g_col[p0] = s.x;
        if (p1 < EMAX) g_col[p1] = s.y;
        if (p2 < EMAX) g_col[p2] = s.z;
        if (p3 < EMAX) g_col[p3] = s.w;
    } else {
        for (int i = base; i < E; i++) {
            int pos = g_rowbeg[dst[i]] + g_seq[i];
            if (pos < EMAX) g_col[pos] = src[i];
        }
    }
}

// ---------------------------------------------------------------- GEMM1: h1 = (x * norm_src) @ W1
// 64 rows/block, 512 threads (16 warps), cp.async double-buffered X tiles.
__global__ void __launch_bounds__(512) k_gemm1(const float* __restrict__ x,
                                               const float* __restrict__ W1, int N) {
    __shared__ __align__(16) float Ws[F * H];        // 32 KB
    __shared__ __align__(16) float Xs[2][64 * 32];   // 16 KB
    const int tid = threadIdx.x;
    const int lane = tid & 31;
    const int w = tid >> 5;          // 0..15
    const int row0 = blockIdx.x * 64;

    for (int i = tid; i < (F * H) / 4; i += 512)
        ((float4*)Ws)[i] = ((const float4*)W1)[i];

    // each thread owns one float4 slot per tile
    const int lrow = tid >> 3;            // 0..63
    const int lf4  = tid & 7;             // float4 idx within 32-float row slice
    const int grow = row0 + lrow;
    const bool valid = (grow < N);
    const float* gsrc = x + (long long)(valid ? grow : 0) * F + lf4 * 4;
    const unsigned sdst0 = (unsigned)__cvta_generic_to_shared(&Xs[0][lrow * 32 + lf4 * 4]);
    const unsigned sdst1 = (unsigned)__cvta_generic_to_shared(&Xs[1][lrow * 32 + lf4 * 4]);
    const int nbytes = valid ? 16 : 0;    // 0 -> zero-fill 16B

    asm volatile("cp.async.cg.shared.global [%0], [%1], 16, %2;"
                 :: "r"(sdst0), "l"(gsrc), "r"(nbytes));
    asm volatile("cp.async.commit_group;");

    float acc[4] = {0.f, 0.f, 0.f, 0.f};

    #pragma unroll
    for (int t = 0; t < 8; t++) {
        if (t < 7) {
            // buffer (t+1)&1 was last read in iter t-1; end-of-iter sync makes this safe
            unsigned sd = ((t + 1) & 1) ? sdst1 : sdst0;
            asm volatile("cp.async.cg.shared.global [%0], [%1], 16, %2;"
                         :: "r"(sd), "l"(gsrc + (t + 1) * 32), "r"(nbytes));
            asm volatile("cp.async.commit_group;");
            asm volatile("cp.async.wait_group 1;");   // tile t arrived
        } else {
            asm volatile("cp.async.wait_group 0;");
        }
        __syncthreads();
        const float* Xc = &Xs[t & 1][0];
        #pragma unroll
        for (int k = 0; k < 32; k += 4) {
            int gk = t * 32 + k;
            float wv0 = Ws[(gk + 0) * H + lane];
            float wv1 = Ws[(gk + 1) * H + lane];
            float wv2 = Ws[(gk + 2) * H + lane];
            float wv3 = Ws[(gk + 3) * H + lane];
            #pragma unroll
            for (int r = 0; r < 4; r++) {
                float4 xv = *(const float4*)&Xc[(w * 4 + r) * 32 + k];
                acc[r] += xv.x * wv0 + xv.y * wv1 + xv.z * wv2 + xv.w * wv3;
            }
        }
        __syncthreads();
    }
    #pragma unroll
    for (int r = 0; r < 4; r++) {
        int row = row0 + w * 4 + r;
        if (row < N) g_h1[row * H + lane] = acc[r] * g_norm_src[row];
    }
}

// ---------------------------------------------------------------- Layer 1 fused:
// per node: agg1 = sum_{e in slice[n]} h1[col[e]];  x1 = relu(agg1*nd + b1) * ns;
// h2[n] = x1 @ W2  (shuffle GEMM, x1 one float per lane)
__global__ void k_layer1(const float* __restrict__ b1, const float* __restrict__ W2, int N) {
    __shared__ float Ws[H * C];   // 5 KB
    const int tid = threadIdx.x;
    const int lane = tid & 31;
    const int w = tid >> 5;
    for (int i = tid; i < H * C; i += 256) Ws[i] = W2[i];
    __syncthreads();

    int n = blockIdx.x * 8 + w;
    if (n >= N) return;

    int beg = g_rowbeg[n];
    int end = beg + g_cnt_dst[n];
    float acc = 0.f;
    int e = beg;
    for (; e + 8 <= end; e += 8) {
        int s0 = g_col[e],     s1 = g_col[e + 1], s2 = g_col[e + 2], s3 = g_col[e + 3];
        int s4 = g_col[e + 4], s5 = g_col[e + 5], s6 = g_col[e + 6], s7 = g_col[e + 7];
        float v0 = g_h1[s0 * H + lane];
        float v1 = g_h1[s1 * H + lane];
        float v2 = g_h1[s2 * H + lane];
        float v3 = g_h1[s3 * H + lane];
        float v4 = g_h1[s4 * H + lane];
        float v5 = g_h1[s5 * H + lane];
        float v6 = g_h1[s6 * H + lane];
        float v7 = g_h1[s7 * H + lane];
        acc += ((v0 + v1) + (v2 + v3)) + ((v4 + v5) + (v6 + v7));
    }
    for (; e < end; e++) acc += g_h1[g_col[e] * H + lane];

    float x1 = fmaxf(fmaf(acc, g_norm_dst[n], b1[lane]), 0.f) * g_norm_src[n];

    float o0 = 0.f, o1 = 0.f;
    #pragma unroll
    for (int k = 0; k < H; k++) {
        float xk = __shfl_sync(0xffffffffu, x1, k);
        o0 = fmaf(xk, Ws[k * C + lane], o0);
        o1 = fmaf(xk, (lane < 8) ? Ws[k * C + 32 + lane] : 0.f, o1);
    }
    g_h2[n * C + lane] = o0;
    if (lane < 8) g_h2[n * C + 32 + lane] = o1;
}

// ---------------------------------------------------------------- Layer 2 fused:
// per node: agg2 = sum h2[col[e]];  v = agg2*nd + b2;  out[n] = log_softmax(v)
__global__ void k_layer2(const float* __restrict__ b2, float* __restrict__ out, int N) {
    const int tid = threadIdx.x;
    const int lane = tid & 31;
    const int w = tid >> 5;
    int n = blockIdx.x * 8 + w;
    if (n >= N) return;

    int beg = g_rowbeg[n];
    int end = beg + g_cnt_dst[n];
    float a0 = 0.f, a1 = 0.f;
    int e = beg;
    for (; e + 8 <= end; e += 8) {
        int s0 = g_col[e],     s1 = g_col[e + 1], s2 = g_col[e + 2], s3 = g_col[e + 3];
        int s4 = g_col[e + 4], s5 = g_col[e + 5], s6 = g_col[e + 6], s7 = g_col[e + 7];
        float u0 = g_h2[s0 * C + lane];
        float u1 = g_h2[s1 * C + lane];
        float u2 = g_h2[s2 * C + lane];
        float u3 = g_h2[s3 * C + lane];
        float u4 = g_h2[s4 * C + lane];
        float u5 = g_h2[s5 * C + lane];
        float u6 = g_h2[s6 * C + lane];
        float u7 = g_h2[s7 * C + lane];
        a0 += ((u0 + u1) + (u2 + u3)) + ((u4 + u5) + (u6 + u7));
        if (lane < 8) {
            float p0 = g_h2[s0 * C + 32 + lane];
            float p1 = g_h2[s1 * C + 32 + lane];
            float p2 = g_h2[s2 * C + 32 + lane];
            float p3 = g_h2[s3 * C + 32 + lane];
            float p4 = g_h2[s4 * C + 32 + lane];
            float p5 = g_h2[s5 * C + 32 + lane];
            float p6 = g_h2[s6 * C + 32 + lane];
            float p7 = g_h2[s7 * C + 32 + lane];
            a1 += ((p0 + p1) + (p2 + p3)) + ((p4 + p5) + (p6 + p7));
        }
    }
    for (; e < end; e++) {
        int s = g_col[e];
        a0 += g_h2[s * C + lane];
        if (lane < 8) a1 += g_h2[s * C + 32 + lane];
    }

    float nd = g_norm_dst[n];
    float v0 = fmaf(a0, nd, b2[lane]);
    float v1 = (lane < 8) ? fmaf(a1, nd, b2[32 + lane]) : -1e30f;

    float m = fmaxf(v0, v1);
    #pragma unroll
    for (int off = 16; off > 0; off >>= 1)
        m = fmaxf(m, __shfl_xor_sync(0xffffffffu, m, off));
    float s = __expf(v0 - m) + ((lane < 8) ? __expf(v1 - m) : 0.f);
    #pragma unroll
    for (int off = 16; off > 0; off >>= 1)
        s += __shfl_xor_sync(0xffffffffu, s, off);
    float lse = m + __logf(s);

    out[n * C + lane] = v0 - lse;
    if (lane < 8) out[n * C + 32 + lane] = v1 - lse;
}

// ---------------------------------------------------------------- launch
extern "C" void kernel_launch(void* const* d_in, const int* in_sizes, int n_in,
                              void* d_out, int out_size) {
    const float* feat = (const float*)d_in[0];
    const int*   src  = (const int*)d_in[1];
    const int*   dst  = (const int*)d_in[2];
    const float* W1   = (const float*)d_in[3];
    const float* b1   = (const float*)d_in[4];
    const float* W2   = (const float*)d_in[5];
    const float* b2   = (const float*)d_in[6];
    float* out = (float*)d_out;

    const int N = in_sizes[0] / F;
    const int E = in_sizes[1];

    k_zero<<<128, 256>>>(N);
    k_pass1<<<(E + 1023) / 1024, 256>>>(src, dst, E);
    k_alloc<<<(N + 255) / 256, 256>>>(N);
    k_pass2<<<(E + 1023) / 1024, 256>>>(src, dst, E);
    k_gemm1<<<(N + 63) / 64, 512>>>(feat, W1, N);
    k_layer1<<<(N + 7) / 8, 256>>>(b1, W2, N);
    k_layer2<<<(N + 7) / 8, 256>>>(b2, out, N);
}

// round 17
// speedup vs baseline: 2.5598x; 1.0394x over previous
#include <cuda_runtime.h>
#include <cuda_bf16.h>

#define NMAX 100000
#define EMAX 3700000
#define F 256
#define H 32
#define C 40

// Scratch (allocation-free rule: __device__ globals)
__device__ __align__(16) int   g_cnt_src[NMAX];
__device__ __align__(16) int   g_cnt_dst[NMAX];
__device__ __align__(16) float g_norm_src[NMAX];
__device__ __align__(16) float g_norm_dst[NMAX];
__device__ __align__(16) int   g_rowbeg[NMAX];
__device__              int    g_total;
__device__ __align__(16) int   g_seq[EMAX];             // per-edge rank within its dst
__device__ __align__(16) int   g_col[EMAX];             // CSR-ish by dst: src indices
__device__ __align__(16) float g_h1[NMAX * H];          // x @ W1 (UNSCALED; ns applied at gather)
__device__ __align__(16) float g_h2[NMAX * C];          // (relu(agg1*nd+b1)*ns) @ W2

// ---------------------------------------------------------------- zero counts
__global__ void k_zero(int N) {
    int i = blockIdx.x * blockDim.x + threadIdx.x;
    int stride = gridDim.x * blockDim.x;
    if (i == 0) g_total = 0;
    for (int t = i; t < N; t += stride) { g_cnt_src[t] = 0; g_cnt_dst[t] = 0; }
}

// ---------------------------------------------------------------- Fused K1: gemm1 (unscaled) || pass1
// Role striping: for b < 2*m, even -> gemm tile b/2, odd -> pass1 chunk b/2;
// leftover blocks take the role with more work. Both roles start in wave 1 and
// use disjoint pipes (DRAM+FMA vs L2 atomics), so pass1 hides under gemm1.
__global__ void __launch_bounds__(512) k_fused1(const float* __restrict__ x,
                                                const float* __restrict__ W1,
                                                const int* __restrict__ src,
                                                const int* __restrict__ dst,
                                                int E, int N, int ngemm, int npass) {
    __shared__ __align__(16) float Ws[F * H];        // 32 KB
    __shared__ __align__(16) float Xs[2][64 * 32];   // 16 KB

    const int b = blockIdx.x;
    const int m = (ngemm < npass) ? ngemm : npass;
    int role, idx;
    if (b < 2 * m) { role = b & 1; idx = b >> 1; }
    else {
        int left = b - 2 * m;
        role = (ngemm > npass) ? 0 : 1;
        idx = m + left;
    }

    if (role == 1) {
        // ---------------- pass1: count + rank (2048 edges per block)
        int base = (idx * 512 + threadIdx.x) * 4;
        if (base + 3 < E) {
            int4 s = *(const int4*)(src + base);
            int4 d = *(const int4*)(dst + base);
            int q0 = atomicAdd(&g_cnt_dst[d.x], 1);
            int q1 = atomicAdd(&g_cnt_dst[d.y], 1);
            int q2 = atomicAdd(&g_cnt_dst[d.z], 1);
            int q3 = atomicAdd(&g_cnt_dst[d.w], 1);
            *(int4*)(g_seq + base) = make_int4(q0, q1, q2, q3);
            atomicAdd(&g_cnt_src[s.x], 1);
            atomicAdd(&g_cnt_src[s.y], 1);
            atomicAdd(&g_cnt_src[s.z], 1);
            atomicAdd(&g_cnt_src[s.w], 1);
        } else {
            for (int i = base; i < E; i++) {
                g_seq[i] = atomicAdd(&g_cnt_dst[dst[i]], 1);
                atomicAdd(&g_cnt_src[src[i]], 1);
            }
        }
        return;
    }

    // ---------------- gemm1: h1 = x @ W1 (NO norm_src), 64 rows per tile
    const int tid = threadIdx.x;
    const int lane = tid & 31;
    const int w = tid >> 5;          // 0..15
    const int row0 = idx * 64;

    for (int i = tid; i < (F * H) / 4; i += 512)
        ((float4*)Ws)[i] = ((const float4*)W1)[i];

    const int lrow = tid >> 3;            // 0..63
    const int lf4  = tid & 7;
    const int grow = row0 + lrow;
    const bool valid = (grow < N);
    const float* gsrc = x + (long long)(valid ? grow : 0) * F + lf4 * 4;
    const unsigned sdst0 = (unsigned)__cvta_generic_to_shared(&Xs[0][lrow * 32 + lf4 * 4]);
    const unsigned sdst1 = (unsigned)__cvta_generic_to_shared(&Xs[1][lrow * 32 + lf4 * 4]);
    const int nbytes = valid ? 16 : 0;    // 0 -> zero-fill 16B

    asm volatile("cp.async.cg.shared.global [%0], [%1], 16, %2;"
                 :: "r"(sdst0), "l"(gsrc), "r"(nbytes));
    asm volatile("cp.async.commit_group;");

    float acc[4] = {0.f, 0.f, 0.f, 0.f};

    #pragma unroll
    for (int t = 0; t < 8; t++) {
        if (t < 7) {
            unsigned sd = ((t + 1) & 1) ? sdst1 : sdst0;
            asm volatile("cp.async.cg.shared.global [%0], [%1], 16, %2;"
                         :: "r"(sd), "l"(gsrc + (t + 1) * 32), "r"(nbytes));
            asm volatile("cp.async.commit_group;");
            asm volatile("cp.async.wait_group 1;");
        } else {
            asm volatile("cp.async.wait_group 0;");
        }
        __syncthreads();
        const float* Xc = &Xs[t & 1][0];
        #pragma unroll
        for (int k = 0; k < 32; k += 4) {
            int gk = t * 32 + k;
            float wv0 = Ws[(gk + 0) * H + lane];
            float wv1 = Ws[(gk + 1) * H + lane];
            float wv2 = Ws[(gk + 2) * H + lane];
            float wv3 = Ws[(gk + 3) * H + lane];
            #pragma unroll
            for (int r = 0; r < 4; r++) {
                float4 xv = *(const float4*)&Xc[(w * 4 + r) * 32 + k];
                acc[r] += xv.x * wv0 + xv.y * wv1 + xv.z * wv2 + xv.w * wv3;
            }
        }
        __syncthreads();
    }
    #pragma unroll
    for (int r = 0; r < 4; r++) {
        int row = row0 + w * 4 + r;
        if (row < N) g_h1[row * H + lane] = acc[r];
    }
}

// ---------------------------------------------------------------- allocate slices + norms
__global__ void k_alloc(int N) {
    int i = blockIdx.x * blockDim.x + threadIdx.x;
    int lane = threadIdx.x & 31;
    int cnt = (i < N) ? g_cnt_dst[i] : 0;

    int incl = cnt;
    #pragma unroll
    for (int off = 1; off < 32; off <<= 1) {
        int v = __shfl_up_sync(0xffffffffu, incl, off);
        if (lane >= off) incl += v;
    }
    int total = __shfl_sync(0xffffffffu, incl, 31);
    int base = 0;
    if (lane == 31 && total > 0) base = atomicAdd(&g_total, total);
    base = __shfl_sync(0xffffffffu, base, 31);

    if (i < N) {
        g_rowbeg[i] = base + incl - cnt;
        g_norm_src[i] = rsqrtf((float)g_cnt_src[i]);   // self-loops guarantee deg >= 1
        g_norm_dst[i] = rsqrtf((float)cnt);
    }
}

// ---------------------------------------------------------------- pass2: scatter fill, no atomics
__global__ void k_pass2(const int* __restrict__ src, const int* __restrict__ dst, int E) {
    int base = (blockIdx.x * blockDim.x + threadIdx.x) * 4;
    if (base + 3 < E) {
        int4 s = *(const int4*)(src + base);
        int4 d = *(const int4*)(dst + base);
        int4 q = *(const int4*)(g_seq + base);
        int p0 = g_rowbeg[d.x] + q.x;
        int p1 = g_rowbeg[d.y] + q.y;
        int p2 = g_rowbeg[d.z] + q.z;
        int p3 = g_rowbeg[d.w] + q.w;
        if (p0 < EMAX) g_col[p0] = s.x;
        if (p1 < EMAX) g_col[p1] = s.y;
        if (p2 < EMAX) g_col[p2] = s.z;
        if (p3 < EMAX) g_col[p3] = s.w;
    } else {
        for (int i = base; i < E; i++) {
            int pos = g_rowbeg[dst[i]] + g_seq[i];
            if (pos < EMAX) g_col[pos] = src[i];
        }
    }
}

// ---------------------------------------------------------------- Layer 1 fused:
// agg1 = sum ns[s] * h1[s];  x1 = relu(agg1*nd + b1) * ns[n];  h2[n] = x1 @ W2
__global__ void k_layer1(const float* __restrict__ b1, const float* __restrict__ W2, int N) {
    __shared__ float Ws[H * C];   // 5 KB
    const int tid = threadIdx.x;
    const int lane = tid & 31;
    const int w = tid >> 5;
    for (int i = tid; i < H * C; i += 256) Ws[i] = W2[i];
    __syncthreads();

    int n = blockIdx.x * 8 + w;
    if (n >= N) return;

    int beg = g_rowbeg[n];
    int end = beg + g_cnt_dst[n];
    float acc = 0.f;
    int e = beg;
    for (; e + 8 <= end; e += 8) {
        int s0 = g_col[e],     s1 = g_col[e + 1], s2 = g_col[e + 2], s3 = g_col[e + 3];
        int s4 = g_col[e + 4], s5 = g_col[e + 5], s6 = g_col[e + 6], s7 = g_col[e + 7];
        float n0 = g_norm_src[s0], n1 = g_norm_src[s1], n2 = g_norm_src[s2], n3 = g_norm_src[s3];
        float n4 = g_norm_src[s4], n5 = g_norm_src[s5], n6 = g_norm_src[s6], n7 = g_norm_src[s7];
        acc = fmaf(n0, g_h1[s0 * H + lane], acc);
        acc = fmaf(n1, g_h1[s1 * H + lane], acc);
        acc = fmaf(n2, g_h1[s2 * H + lane], acc);
        acc = fmaf(n3, g_h1[s3 * H + lane], acc);
        acc = fmaf(n4, g_h1[s4 * H + lane], acc);
        acc = fmaf(n5, g_h1[s5 * H + lane], acc);
        acc = fmaf(n6, g_h1[s6 * H + lane], acc);
        acc = fmaf(n7, g_h1[s7 * H + lane], acc);
    }
    for (; e < end; e++) {
        int s = g_col[e];
        acc = fmaf(g_norm_src[s], g_h1[s * H + lane], acc);
    }

    float x1 = fmaxf(fmaf(acc, g_norm_dst[n], b1[lane]), 0.f) * g_norm_src[n];

    float o0 = 0.f, o1 = 0.f;
    #pragma unroll
    for (int k = 0; k < H; k++) {
        float xk = __shfl_sync(0xffffffffu, x1, k);
        o0 = fmaf(xk, Ws[k * C + lane], o0);
        o1 = fmaf(xk, (lane < 8) ? Ws[k * C + 32 + lane] : 0.f, o1);
    }
    g_h2[n * C + lane] = o0;
    if (lane < 8) g_h2[n * C + 32 + lane] = o1;
}

// ---------------------------------------------------------------- Layer 2 fused:
// agg2 = sum h2[col[e]];  v = agg2*nd + b2;  out[n] = log_softmax(v)
__global__ void k_layer2(const float* __restrict__ b2, float* __restrict__ out, int N) {
    const int tid = threadIdx.x;
    const int lane = tid & 31;
    const int w = tid >> 5;
    int n = blockIdx.x * 8 + w;
    if (n >= N) return;

    int beg = g_rowbeg[n];
    int end = beg + g_cnt_dst[n];
    float a0 = 0.f, a1 = 0.f;
    int e = beg;
    for (; e + 8 <= end; e += 8) {
        int s0 = g_col[e],     s1 = g_col[e + 1], s2 = g_col[e + 2], s3 = g_col[e + 3];
        int s4 = g_col[e + 4], s5 = g_col[e + 5], s6 = g_col[e + 6], s7 = g_col[e + 7];
        float u0 = g_h2[s0 * C + lane];
        float u1 = g_h2[s1 * C + lane];
        float u2 = g_h2[s2 * C + lane];
        float u3 = g_h2[s3 * C + lane];
        float u4 = g_h2[s4 * C + lane];
        float u5 = g_h2[s5 * C + lane];
        float u6 = g_h2[s6 * C + lane];
        float u7 = g_h2[s7 * C + lane];
        a0 += ((u0 + u1) + (u2 + u3)) + ((u4 + u5) + (u6 + u7));
        if (lane < 8) {
            float p0 = g_h2[s0 * C + 32 + lane];
            float p1 = g_h2[s1 * C + 32 + lane];
            float p2 = g_h2[s2 * C + 32 + lane];
            float p3 = g_h2[s3 * C + 32 + lane];
            float p4 = g_h2[s4 * C + 32 + lane];
            float p5 = g_h2[s5 * C + 32 + lane];
            float p6 = g_h2[s6 * C + 32 + lane];
            float p7 = g_h2[s7 * C + 32 + lane];
            a1 += ((p0 + p1) + (p2 + p3)) + ((p4 + p5) + (p6 + p7));
        }
    }
    for (; e < end; e++) {
        int s = g_col[e];
        a0 += g_h2[s * C + lane];
        if (lane < 8) a1 += g_h2[s * C + 32 + lane];
    }

    float nd = g_norm_dst[n];
    float v0 = fmaf(a0, nd, b2[lane]);
    float v1 = (lane < 8) ? fmaf(a1, nd, b2[32 + lane]) : -1e30f;

    float m = fmaxf(v0, v1);
    #pragma unroll
    for (int off = 16; off > 0; off >>= 1)
        m = fmaxf(m, __shfl_xor_sync(0xffffffffu, m, off));
    float s = __expf(v0 - m) + ((lane < 8) ? __expf(v1 - m) : 0.f);
    #pragma unroll
    for (int off = 16; off > 0; off >>= 1)
        s += __shfl_xor_sync(0xffffffffu, s, off);
    float lse = m + __logf(s);

    out[n * C + lane] = v0 - lse;
    if (lane < 8) out[n * C + 32 + lane] = v1 - lse;
}

// ---------------------------------------------------------------- launch
extern "C" void kernel_launch(void* const* d_in, const int* in_sizes, int n_in,
                              void* d_out, int out_size) {
    const float* feat = (const float*)d_in[0];
    const int*   src  = (const int*)d_in[1];
    const int*   dst  = (const int*)d_in[2];
    const float* W1   = (const float*)d_in[3];
    const float* b1   = (const float*)d_in[4];
    const float* W2   = (const float*)d_in[5];
    const float* b2   = (const float*)d_in[6];
    float* out = (float*)d_out;

    const int N = in_sizes[0] / F;
    const int E = in_sizes[1];

    const int ngemm = (N + 63) / 64;
    const int npass = (E + 2047) / 2048;

    k_zero<<<128, 256>>>(N);
    k_fused1<<<ngemm + npass, 512>>>(feat, W1, src, dst, E, N, ngemm, npass);
    k_alloc<<<(N + 255) / 256, 256>>>(N);
    k_pass2<<<(E + 1023) / 1024, 256>>>(src, dst, E);
    k_layer1<<<(N + 7) / 8, 256>>>(b1, W2, N);
    k_layer2<<<(N + 7) / 8, 256>>>(b2, out, N);
}